// round 16
// baseline (speedup 1.0000x reference)
#include <cuda_runtime.h>
#include <cuda_fp16.h>
#include <math.h>
#include <stdint.h>

#define B_ 4
#define T_ 2048
#define C_ 1024
#define H_ 16
#define D_ 64
#define C3_ (3 * C_)
#define M_ (B_ * T_)
#define K2_ (C_ / 2)          // 512 words (fp16 pairs)
#define KQV_W (C3_ / 2)       // 1536 words per token row
#define YW (C_ / 2)           // 512 words per token row

// ---------------------------------------------------------------------------
// Scratch (no cudaMalloc allowed)
// ---------------------------------------------------------------------------
__device__ uint32_t g_xh[(size_t)M_ * K2_];
__device__ uint32_t g_wkqvTh[(size_t)C3_ * K2_];
__device__ uint32_t g_wprojTh[(size_t)C_ * K2_];
__device__ uint32_t g_kqvh[(size_t)M_ * KQV_W];
__device__ uint32_t g_yh[(size_t)M_ * YW];

__device__ __forceinline__ uint32_t pack_h2(float a, float b) {
    __half2 h = __floats2half2_rn(a, b);
    return *reinterpret_cast<uint32_t*>(&h);
}
__device__ __forceinline__ float ex2(float x) {
    float y;
    asm("ex2.approx.f32 %0, %1;" : "=f"(y) : "f"(x));
    return y;
}

// mma.sync m16n8k16 fp16 in, fp32 accum
__device__ __forceinline__ void mma_f16(
    float c[4], uint32_t a0, uint32_t a1, uint32_t a2, uint32_t a3,
    uint32_t b0, uint32_t b1)
{
    asm volatile(
        "mma.sync.aligned.m16n8k16.row.col.f32.f16.f16.f32 "
        "{%0,%1,%2,%3}, {%4,%5,%6,%7}, {%8,%9}, {%0,%1,%2,%3};"
        : "+f"(c[0]), "+f"(c[1]), "+f"(c[2]), "+f"(c[3])
        : "r"(a0), "r"(a1), "r"(a2), "r"(a3), "r"(b0), "r"(b1));
}

// ldmatrix x4
__device__ __forceinline__ void ldsm_x4(uint32_t r[4], uint32_t addr) {
    asm volatile(
        "ldmatrix.sync.aligned.m8n8.x4.shared.b16 {%0,%1,%2,%3}, [%4];"
        : "=r"(r[0]), "=r"(r[1]), "=r"(r[2]), "=r"(r[3]) : "r"(addr));
}
// ldmatrix x4 transposed (V fragments from natural [token][d] layout)
__device__ __forceinline__ void ldsm_x4_trans(uint32_t r[4], uint32_t addr) {
    asm volatile(
        "ldmatrix.sync.aligned.m8n8.x4.trans.shared.b16 {%0,%1,%2,%3}, [%4];"
        : "=r"(r[0]), "=r"(r[1]), "=r"(r[2]), "=r"(r[3]) : "r"(addr));
}

// cp.async 16B, L1-bypass
__device__ __forceinline__ void cp_async16(uint32_t smem_addr, const void* gptr) {
    asm volatile("cp.async.cg.shared.global [%0], [%1], 16;"
                 :: "r"(smem_addr), "l"(gptr));
}
#define CP_COMMIT() asm volatile("cp.async.commit_group;" ::: "memory")
#define CP_WAIT(N) asm volatile("cp.async.wait_group %0;" :: "n"(N) : "memory")

// ---------------------------------------------------------------------------
// fp32 -> fp16 pairs
// ---------------------------------------------------------------------------
__global__ void __launch_bounds__(256) cvt_f32_to_h2(
    const float* __restrict__ in, uint32_t* __restrict__ out, int nw)
{
    int i = blockIdx.x * blockDim.x + threadIdx.x;
    if (i >= nw) return;
    float2 v = ((const float2*)in)[i];
    out[i] = pack_h2(v.x, v.y);
}

// ---------------------------------------------------------------------------
// Transpose + fp16: W [K,N] fp32 -> Wt [N,K] fp16
// ---------------------------------------------------------------------------
__global__ void __launch_bounds__(256) transpose_h(
    const float* __restrict__ W, __half* __restrict__ Wt, int K, int N)
{
    __shared__ float tile[32][33];
    const int n0 = blockIdx.x * 32, k0 = blockIdx.y * 32;
    #pragma unroll
    for (int i = threadIdx.y; i < 32; i += 8)
        tile[i][threadIdx.x] = W[(size_t)(k0 + i) * N + n0 + threadIdx.x];
    __syncthreads();
    #pragma unroll
    for (int i = threadIdx.y; i < 32; i += 8)
        Wt[(size_t)(n0 + i) * K + k0 + threadIdx.x] = __float2half_rn(tile[threadIdx.x][i]);
}

// ---------------------------------------------------------------------------
// fp16 GEMM: CTA tile 128x64, 128 threads (4 warps 2x2, warp 64x32),
// 3-stage cp.async pipeline (dynamic smem), ldmatrix frags:
//   C[M,N] = A[M,K] @ Bt[N,K]^T + bias[N]
// 4 CTAs/SM -> 4 independent 128-thread barrier domains per SM.
// ---------------------------------------------------------------------------
#define GBK2 16
#define SP 20
#define GAROWS 128
#define GBROWS 64
#define GASTG (GAROWS * SP)             // 2560 words
#define GBSTG (GBROWS * SP)             // 1280 words
#define GSTG (GASTG + GBSTG)            // 3840 words per stage
#define GSTGB (GSTG * 4)
#define GNSTG 3
#define GSM_DYN (GNSTG * GSTGB)         // 46080 bytes

__global__ void __launch_bounds__(128, 4) gemm_f16_mma(
    const uint32_t* __restrict__ A, const uint32_t* __restrict__ Bt,
    const float* __restrict__ bias, void* __restrict__ Cout,
    int M, int N, int K2, int outHalf)
{
    extern __shared__ uint32_t dsm[];

    const int tid = threadIdx.x;
    const int wid = tid >> 5;
    const int lane = tid & 31;
    const int g = lane >> 2;
    const int q = lane & 3;
    const int i8 = lane & 7, mh = lane >> 3;

    const int wm = (wid >> 1) * 64;    // 0 or 64
    const int wn = (wid & 1) * 32;     // 0 or 32

    const int mtile = blockIdx.y;
    const int ntile = blockIdx.x;

    const uint32_t* Ag = A + (size_t)mtile * 128 * K2;
    const uint32_t* Bg = Bt + (size_t)ntile * 64 * K2;

    const uint32_t asA = (uint32_t)__cvta_generic_to_shared(dsm);
    const uint32_t asB = asA + GASTG * 4;   // B region within each stage

    uint32_t aAddr[4];
    #pragma unroll
    for (int mi = 0; mi < 4; mi++)
        aAddr[mi] = asA + ((wm + mi * 16 + i8 + (mh & 1) * 8) * SP + (mh >> 1) * 4) * 4;
    uint32_t bAddr[2];
    #pragma unroll
    for (int j = 0; j < 2; j++)
        bAddr[j] = asB + ((wn + (2 * j + (mh >> 1)) * 8 + i8) * SP + (mh & 1) * 4) * 4;

    const int lr = tid >> 2, lc = tid & 3;   // A rows 0..31(+32i), B rows 0..31(+32i)
    const int nchunk = K2 / GBK2;

    // prologue: stages 0,1
    #pragma unroll
    for (int s = 0; s < 2; s++) {
        const int k0 = s * GBK2;
        const uint32_t boff = (uint32_t)s * GSTGB;
        #pragma unroll
        for (int i = 0; i < 4; i++) {          // A: 128 rows
            const int r = lr + i * 32;
            cp_async16(asA + boff + (uint32_t)(r * SP + lc * 4) * 4,
                       Ag + (size_t)r * K2 + k0 + lc * 4);
        }
        #pragma unroll
        for (int i = 0; i < 2; i++) {          // B: 64 rows
            const int r = lr + i * 32;
            cp_async16(asB + boff + (uint32_t)(r * SP + lc * 4) * 4,
                       Bg + (size_t)r * K2 + k0 + lc * 4);
        }
        CP_COMMIT();
    }

    float acc[4][4][4];
    #pragma unroll
    for (int mi = 0; mi < 4; mi++)
        #pragma unroll
        for (int ni = 0; ni < 4; ni++)
            #pragma unroll
            for (int r = 0; r < 4; r++) acc[mi][ni][r] = 0.f;

    int stage = 0;
    for (int ch = 0; ch < nchunk; ch++) {
        CP_WAIT(1);
        __syncthreads();

        if (ch + 2 < nchunk) {
            const int k0 = (ch + 2) * GBK2;
            int ps = stage + 2; if (ps >= GNSTG) ps -= GNSTG;
            const uint32_t boff = (uint32_t)ps * GSTGB;
            #pragma unroll
            for (int i = 0; i < 4; i++) {
                const int r = lr + i * 32;
                cp_async16(asA + boff + (uint32_t)(r * SP + lc * 4) * 4,
                           Ag + (size_t)r * K2 + k0 + lc * 4);
            }
            #pragma unroll
            for (int i = 0; i < 2; i++) {
                const int r = lr + i * 32;
                cp_async16(asB + boff + (uint32_t)(r * SP + lc * 4) * 4,
                           Bg + (size_t)r * K2 + k0 + lc * 4);
            }
        }
        CP_COMMIT();

        const uint32_t bufoff = (uint32_t)stage * GSTGB;
        #pragma unroll
        for (int ks = 0; ks < GBK2; ks += 8) {
            const uint32_t coff = bufoff + ks * 4;
            uint32_t af[4][4], bf[4][2];
            #pragma unroll
            for (int mi = 0; mi < 4; mi++)
                ldsm_x4(af[mi], aAddr[mi] + coff);
            #pragma unroll
            for (int j = 0; j < 2; j++) {
                uint32_t t[4];
                ldsm_x4(t, bAddr[j] + coff);
                bf[2 * j][0] = t[0]; bf[2 * j][1] = t[1];
                bf[2 * j + 1][0] = t[2]; bf[2 * j + 1][1] = t[3];
            }
            #pragma unroll
            for (int mi = 0; mi < 4; mi++)
                #pragma unroll
                for (int ni = 0; ni < 4; ni++)
                    mma_f16(acc[mi][ni], af[mi][0], af[mi][1], af[mi][2], af[mi][3],
                            bf[ni][0], bf[ni][1]);
        }
        if (++stage == GNSTG) stage = 0;
    }

    const int rowbase = mtile * 128 + wm;
    const int colbase = ntile * 64 + wn;
    if (outHalf) {
        uint32_t* Ch = (uint32_t*)Cout;
        const int Nw = N >> 1;
        #pragma unroll
        for (int mi = 0; mi < 4; mi++) {
            #pragma unroll
            for (int ni = 0; ni < 4; ni++) {
                const int col = colbase + ni * 8 + 2 * q;
                const float bx = bias[col], by = bias[col + 1];
                const int r0 = rowbase + mi * 16 + g;
                const int wcol = col >> 1;
                Ch[(size_t)r0 * Nw + wcol] = pack_h2(acc[mi][ni][0] + bx, acc[mi][ni][1] + by);
                Ch[(size_t)(r0 + 8) * Nw + wcol] = pack_h2(acc[mi][ni][2] + bx, acc[mi][ni][3] + by);
            }
        }
    } else {
        float* Cf = (float*)Cout;
        #pragma unroll
        for (int mi = 0; mi < 4; mi++) {
            #pragma unroll
            for (int ni = 0; ni < 4; ni++) {
                const int col = colbase + ni * 8 + 2 * q;
                const float bx = bias[col], by = bias[col + 1];
                const int r0 = rowbase + mi * 16 + g;
                float2 v0 = make_float2(acc[mi][ni][0] + bx, acc[mi][ni][1] + by);
                float2 v1 = make_float2(acc[mi][ni][2] + bx, acc[mi][ni][3] + by);
                *(float2*)(Cf + (size_t)r0 * N + col) = v0;
                *(float2*)(Cf + (size_t)(r0 + 8) * N + col) = v1;
            }
        }
    }
}

// ---------------------------------------------------------------------------
// fp16 flash attention (64 queries/CTA, 128 threads):
// cp.async double-buffered K/V, V via ldmatrix.trans, P in registers,
// log2 softmax, mask fast-path on fully-valid non-diagonal tiles.
// ---------------------------------------------------------------------------
#define FBQ 64
#define FKV 64
#define AP 36
#define ATILE (FKV * AP)
#define ATILEB (ATILE * 4)

__global__ void __launch_bounds__(128) flash_attn_f16(
    const uint32_t* __restrict__ kqvh, const int* __restrict__ pmask,
    uint32_t* __restrict__ yh)
{
    __shared__ uint32_t Ksh[2][ATILE];
    __shared__ uint32_t Vsh[2][ATILE];
    __shared__ uint32_t Qsh[FBQ * AP];
    __shared__ int pm_sh[2][FKV];

    const int qt = (T_ / FBQ - 1) - blockIdx.x;
    const int bh = blockIdx.y;
    const int b = bh / H_, h = bh % H_;
    const int tid = threadIdx.x;
    const int wid = tid >> 5, lane = tid & 31;
    const int g = lane >> 2, q = lane & 3;
    const int i8 = lane & 7, mh = lane >> 3;
    const int m0 = wid * 16;

    const uint32_t* baseW = kqvh + (size_t)b * T_ * KQV_W + h * 32;
    const int* pmrow = pmask + b * T_;

    const uint32_t sK = (uint32_t)__cvta_generic_to_shared(&Ksh[0][0]);
    const uint32_t sV = (uint32_t)__cvta_generic_to_shared(&Vsh[0][0]);
    const uint32_t sPM = (uint32_t)__cvta_generic_to_shared(&pm_sh[0][0]);

    uint32_t kAddr[4];
    #pragma unroll
    for (int j = 0; j < 4; j++)
        kAddr[j] = sK + (((2 * j + (mh >> 1)) * 8 + i8) * AP + (mh & 1) * 4) * 4;
    uint32_t vAddr[4];
    #pragma unroll
    for (int j = 0; j < 4; j++)
        vAddr[j] = sV + ((i8 + (mh & 1) * 8) * AP + (2 * j + (mh >> 1)) * 4) * 4;

    const int ir = tid >> 3, ic = tid & 7;

    // ---- load Q tile, scale by log2(e)/sqrt(D) ----
    const float qscale = 0.125f * 1.4426950408889634f;
    #pragma unroll
    for (int it = 0; it < 4; it++) {
        const int idx = tid + it * 128;
        const int r = idx >> 3, c4 = idx & 7;
        uint4 w = *(const uint4*)(baseW + (C_ / 2) + (size_t)(qt * FBQ + r) * KQV_W + c4 * 4);
        uint32_t* ww = &w.x;
        uint32_t out[4];
        #pragma unroll
        for (int k = 0; k < 4; k++) {
            __half2 hv = *reinterpret_cast<__half2*>(&ww[k]);
            float2 f = __half22float2(hv);
            out[k] = pack_h2(f.x * qscale, f.y * qscale);
        }
        *(uint4*)&Qsh[r * AP + c4 * 4] = *(uint4*)out;
    }

    // prologue: prefetch tile 0 into buf 0
    {
        #pragma unroll
        for (int it = 0; it < 4; it++) {
            const int r = ir + it * 16;
            const uint32_t doff = (uint32_t)(r * AP + ic * 4) * 4;
            cp_async16(sK + doff, baseW + (size_t)r * KQV_W + ic * 4);
            cp_async16(sV + doff, baseW + 2 * (C_ / 2) + (size_t)r * KQV_W + ic * 4);
        }
        if (tid < 16) cp_async16(sPM + tid * 16, pmrow + tid * 4);
        CP_COMMIT();
    }
    __syncthreads();

    // ---- Q fragments ----
    uint32_t qf[4][4];
    #pragma unroll
    for (int kk = 0; kk < 4; kk++) {
        qf[kk][0] = Qsh[(m0 + g) * AP + kk * 8 + q];
        qf[kk][1] = Qsh[(m0 + 8 + g) * AP + kk * 8 + q];
        qf[kk][2] = Qsh[(m0 + g) * AP + kk * 8 + q + 4];
        qf[kk][3] = Qsh[(m0 + 8 + g) * AP + kk * 8 + q + 4];
    }

    float o[8][4];
    #pragma unroll
    for (int ni = 0; ni < 8; ni++)
        #pragma unroll
        for (int r = 0; r < 4; r++) o[ni][r] = 0.f;

    float mr0 = -INFINITY, mr1 = -INFINITY;
    float l0 = 0.f, l1 = 0.f;

    const int r0g = qt * FBQ + m0 + g;
    const int r1g = r0g + 8;

    for (int kt = 0; kt <= qt; kt++) {
        const int cur = kt & 1;
        const int kbase = kt * FKV;

        if (kt < qt) {
            const int nb = kbase + FKV;
            const uint32_t boff = (uint32_t)((cur ^ 1) * ATILE) * 4;
            #pragma unroll
            for (int it = 0; it < 4; it++) {
                const int r = ir + it * 16;
                const uint32_t doff = boff + (uint32_t)(r * AP + ic * 4) * 4;
                cp_async16(sK + doff, baseW + (size_t)(nb + r) * KQV_W + ic * 4);
                cp_async16(sV + doff, baseW + 2 * (C_ / 2) + (size_t)(nb + r) * KQV_W + ic * 4);
            }
            if (tid < 16) cp_async16(sPM + (cur ^ 1) * 256 + tid * 16, pmrow + nb + tid * 4);
            CP_COMMIT();
            CP_WAIT(1);
        } else {
            CP_WAIT(0);
        }
        __syncthreads();

        const uint32_t bufoff = (uint32_t)cur * ATILEB;

        // ---- S = Q K^T ----
        float s[8][4];
        #pragma unroll
        for (int ni = 0; ni < 8; ni++)
            #pragma unroll
            for (int r = 0; r < 4; r++) s[ni][r] = 0.f;

        #pragma unroll
        for (int kk = 0; kk < 4; kk++) {
            const uint32_t coff = bufoff + kk * 32;
            #pragma unroll
            for (int j = 0; j < 4; j++) {
                uint32_t t[4];
                ldsm_x4(t, kAddr[j] + coff);
                mma_f16(s[2 * j],     qf[kk][0], qf[kk][1], qf[kk][2], qf[kk][3], t[0], t[1]);
                mma_f16(s[2 * j + 1], qf[kk][0], qf[kk][1], qf[kk][2], qf[kk][3], t[2], t[3]);
            }
        }

        // ---- mask + tile max (fast path: fully-valid, non-diagonal tile) ----
        const bool diag = (kt == qt);
        const bool allv = __all_sync(0xffffffffu,
            (pm_sh[cur][lane] != 0) & (pm_sh[cur][lane + 32] != 0));
        float mt0 = -INFINITY, mt1 = -INFINITY;
        if (!diag && allv) {
            #pragma unroll
            for (int ni = 0; ni < 8; ni++) {
                mt0 = fmaxf(mt0, fmaxf(s[ni][0], s[ni][1]));
                mt1 = fmaxf(mt1, fmaxf(s[ni][2], s[ni][3]));
            }
        } else {
            #pragma unroll
            for (int ni = 0; ni < 8; ni++) {
                const int c0 = ni * 8 + 2 * q, c1 = c0 + 1;
                const bool pm0 = pm_sh[cur][c0] != 0, pm1 = pm_sh[cur][c1] != 0;
                const int gc0 = kbase + c0, gc1 = kbase + c1;
                if (!(pm0 && (!diag || gc0 <= r0g))) s[ni][0] = -1e30f;
                if (!(pm1 && (!diag || gc1 <= r0g))) s[ni][1] = -1e30f;
                if (!(pm0 && (!diag || gc0 <= r1g))) s[ni][2] = -1e30f;
                if (!(pm1 && (!diag || gc1 <= r1g))) s[ni][3] = -1e30f;
                mt0 = fmaxf(mt0, fmaxf(s[ni][0], s[ni][1]));
                mt1 = fmaxf(mt1, fmaxf(s[ni][2], s[ni][3]));
            }
        }
        mt0 = fmaxf(mt0, __shfl_xor_sync(0xffffffffu, mt0, 1));
        mt0 = fmaxf(mt0, __shfl_xor_sync(0xffffffffu, mt0, 2));
        mt1 = fmaxf(mt1, __shfl_xor_sync(0xffffffffu, mt1, 1));
        mt1 = fmaxf(mt1, __shfl_xor_sync(0xffffffffu, mt1, 2));

        const float mn0 = fmaxf(mr0, mt0), mn1 = fmaxf(mr1, mt1);
        const float ms0 = (mn0 < -1e29f) ? 0.f : mn0;
        const float ms1 = (mn1 < -1e29f) ? 0.f : mn1;
        const float corr0 = ex2(mr0 - ms0);
        const float corr1 = ex2(mr1 - ms1);
        mr0 = mn0; mr1 = mn1;
        l0 *= corr0; l1 *= corr1;
        #pragma unroll
        for (int ni = 0; ni < 8; ni++) {
            o[ni][0] *= corr0; o[ni][1] *= corr0;
            o[ni][2] *= corr1; o[ni][3] *= corr1;
        }

        // ---- P = 2^(S-m) into A-fragment registers ----
        uint32_t pf[8][2];
        #pragma unroll
        for (int ni = 0; ni < 8; ni++) {
            float p0 = ex2(s[ni][0] - ms0);
            float p1 = ex2(s[ni][1] - ms0);
            float p2 = ex2(s[ni][2] - ms1);
            float p3 = ex2(s[ni][3] - ms1);
            l0 += p0 + p1; l1 += p2 + p3;
            pf[ni][0] = pack_h2(p0, p1);
            pf[ni][1] = pack_h2(p2, p3);
        }

        // ---- O += P V  (B frags via ldmatrix.trans from natural V rows) ----
        #pragma unroll
        for (int kk = 0; kk < 4; kk++) {
            const uint32_t coff = bufoff + (uint32_t)(kk * 16 * AP) * 4;
            const uint32_t a0 = pf[2 * kk][0], a1 = pf[2 * kk][1];
            const uint32_t a2 = pf[2 * kk + 1][0], a3 = pf[2 * kk + 1][1];
            #pragma unroll
            for (int j = 0; j < 4; j++) {
                uint32_t t[4];
                ldsm_x4_trans(t, vAddr[j] + coff);
                mma_f16(o[2 * j],     a0, a1, a2, a3, t[0], t[1]);
                mma_f16(o[2 * j + 1], a0, a1, a2, a3, t[2], t[3]);
            }
        }
        __syncthreads();
    }

    // ---- finalize ----
    l0 += __shfl_xor_sync(0xffffffffu, l0, 1);
    l0 += __shfl_xor_sync(0xffffffffu, l0, 2);
    l1 += __shfl_xor_sync(0xffffffffu, l1, 1);
    l1 += __shfl_xor_sync(0xffffffffu, l1, 2);
    const float inv0 = 1.f / l0, inv1 = 1.f / l1;

    #pragma unroll
    for (int ni = 0; ni < 8; ni++) {
        const int wcol = h * 32 + ni * 4 + q;
        yh[(size_t)(b * T_ + r0g) * YW + wcol] = pack_h2(o[ni][0] * inv0, o[ni][1] * inv0);
        yh[(size_t)(b * T_ + r1g) * YW + wcol] = pack_h2(o[ni][2] * inv1, o[ni][3] * inv1);
    }
}

// ---------------------------------------------------------------------------
extern "C" void kernel_launch(void* const* d_in, const int* in_sizes, int n_in,
                              void* d_out, int out_size)
{
    const float* x      = (const float*)d_in[0];
    const float* W_kqv  = (const float*)d_in[1];
    const float* b_kqv  = (const float*)d_in[2];
    const float* W_proj = (const float*)d_in[3];
    const float* b_proj = (const float*)d_in[4];
    const int*   pmask  = (const int*)d_in[5];
    float* out = (float*)d_out;

    uint32_t *xh, *wkqvTh, *wprojTh, *kqvh, *yh;
    cudaGetSymbolAddress((void**)&xh, g_xh);
    cudaGetSymbolAddress((void**)&wkqvTh, g_wkqvTh);
    cudaGetSymbolAddress((void**)&wprojTh, g_wprojTh);
    cudaGetSymbolAddress((void**)&kqvh, g_kqvh);
    cudaGetSymbolAddress((void**)&yh, g_yh);

    cudaFuncSetAttribute(gemm_f16_mma,
                         cudaFuncAttributeMaxDynamicSharedMemorySize, GSM_DYN);

    // 0) convert x and weights to fp16
    {
        int nw = M_ * C_ / 2;
        cvt_f32_to_h2<<<(nw + 255) / 256, 256>>>(x, xh, nw);
        dim3 g1(C3_ / 32, C_ / 32);
        transpose_h<<<g1, dim3(32, 8)>>>(W_kqv, (__half*)wkqvTh, C_, C3_);
        dim3 g2(C_ / 32, C_ / 32);
        transpose_h<<<g2, dim3(32, 8)>>>(W_proj, (__half*)wprojTh, C_, C_);
    }
    // 1) kqv = x @ W_kqv + b_kqv
    {
        dim3 grid(C3_ / 64, M_ / 128);
        gemm_f16_mma<<<grid, 128, GSM_DYN>>>(xh, wkqvTh, b_kqv, kqvh, M_, C3_, K2_, 1);
    }
    // 2) flash attention (64 queries/CTA, 128 threads)
    {
        dim3 grid(T_ / FBQ, B_ * H_);
        flash_attn_f16<<<grid, 128>>>(kqvh, pmask, yh);
    }
    // 3) out = y @ W_proj + b_proj
    {
        dim3 grid(C_ / 64, M_ / 128);
        gemm_f16_mma<<<grid, 128, GSM_DYN>>>(yh, wprojTh, b_proj, out, M_, C_, K2_, 0);
    }
}

// round 17
// speedup vs baseline: 1.0220x; 1.0220x over previous
#include <cuda_runtime.h>
#include <cuda_fp16.h>
#include <math.h>
#include <stdint.h>

#define B_ 4
#define T_ 2048
#define C_ 1024
#define H_ 16
#define D_ 64
#define C3_ (3 * C_)
#define M_ (B_ * T_)
#define K2_ (C_ / 2)          // 512 words (fp16 pairs)
#define KQV_W (C3_ / 2)       // 1536 words per token row
#define YW (C_ / 2)           // 512 words per token row

// ---------------------------------------------------------------------------
// Scratch (no cudaMalloc allowed)
// ---------------------------------------------------------------------------
__device__ uint32_t g_xh[(size_t)M_ * K2_];
__device__ uint32_t g_wkqvTh[(size_t)C3_ * K2_];
__device__ uint32_t g_wprojTh[(size_t)C_ * K2_];
__device__ uint32_t g_kqvh[(size_t)M_ * KQV_W];
__device__ uint32_t g_yh[(size_t)M_ * YW];

__device__ __forceinline__ uint32_t pack_h2(float a, float b) {
    __half2 h = __floats2half2_rn(a, b);
    return *reinterpret_cast<uint32_t*>(&h);
}
__device__ __forceinline__ float ex2(float x) {
    float y;
    asm("ex2.approx.f32 %0, %1;" : "=f"(y) : "f"(x));
    return y;
}
// packed fp16x2 2^x
__device__ __forceinline__ uint32_t ex2_h2(uint32_t x) {
    uint32_t y;
    asm("ex2.approx.f16x2 %0, %1;" : "=r"(y) : "r"(x));
    return y;
}

// mma.sync m16n8k16 fp16 in, fp32 accum
__device__ __forceinline__ void mma_f16(
    float c[4], uint32_t a0, uint32_t a1, uint32_t a2, uint32_t a3,
    uint32_t b0, uint32_t b1)
{
    asm volatile(
        "mma.sync.aligned.m16n8k16.row.col.f32.f16.f16.f32 "
        "{%0,%1,%2,%3}, {%4,%5,%6,%7}, {%8,%9}, {%0,%1,%2,%3};"
        : "+f"(c[0]), "+f"(c[1]), "+f"(c[2]), "+f"(c[3])
        : "r"(a0), "r"(a1), "r"(a2), "r"(a3), "r"(b0), "r"(b1));
}

// ldmatrix x4
__device__ __forceinline__ void ldsm_x4(uint32_t r[4], uint32_t addr) {
    asm volatile(
        "ldmatrix.sync.aligned.m8n8.x4.shared.b16 {%0,%1,%2,%3}, [%4];"
        : "=r"(r[0]), "=r"(r[1]), "=r"(r[2]), "=r"(r[3]) : "r"(addr));
}
// ldmatrix x4 transposed (V fragments from natural [token][d] layout)
__device__ __forceinline__ void ldsm_x4_trans(uint32_t r[4], uint32_t addr) {
    asm volatile(
        "ldmatrix.sync.aligned.m8n8.x4.trans.shared.b16 {%0,%1,%2,%3}, [%4];"
        : "=r"(r[0]), "=r"(r[1]), "=r"(r[2]), "=r"(r[3]) : "r"(addr));
}

// cp.async 16B, L1-bypass
__device__ __forceinline__ void cp_async16(uint32_t smem_addr, const void* gptr) {
    asm volatile("cp.async.cg.shared.global [%0], [%1], 16;"
                 :: "r"(smem_addr), "l"(gptr));
}
#define CP_COMMIT() asm volatile("cp.async.commit_group;" ::: "memory")
#define CP_WAIT(N) asm volatile("cp.async.wait_group %0;" :: "n"(N) : "memory")

// ---------------------------------------------------------------------------
// fp32 -> fp16 pairs
// ---------------------------------------------------------------------------
__global__ void __launch_bounds__(256) cvt_f32_to_h2(
    const float* __restrict__ in, uint32_t* __restrict__ out, int nw)
{
    int i = blockIdx.x * blockDim.x + threadIdx.x;
    if (i >= nw) return;
    float2 v = ((const float2*)in)[i];
    out[i] = pack_h2(v.x, v.y);
}

// ---------------------------------------------------------------------------
// Transpose + fp16: W [K,N] fp32 -> Wt [N,K] fp16
// ---------------------------------------------------------------------------
__global__ void __launch_bounds__(256) transpose_h(
    const float* __restrict__ W, __half* __restrict__ Wt, int K, int N)
{
    __shared__ float tile[32][33];
    const int n0 = blockIdx.x * 32, k0 = blockIdx.y * 32;
    #pragma unroll
    for (int i = threadIdx.y; i < 32; i += 8)
        tile[i][threadIdx.x] = W[(size_t)(k0 + i) * N + n0 + threadIdx.x];
    __syncthreads();
    #pragma unroll
    for (int i = threadIdx.y; i < 32; i += 8)
        Wt[(size_t)(n0 + i) * K + k0 + threadIdx.x] = __float2half_rn(tile[threadIdx.x][i]);
}

// ---------------------------------------------------------------------------
// fp16 GEMM: 4-stage cp.async pipeline (dynamic smem), ldmatrix frags:
//   C[M,N] = A[M,K] @ Bt[N,K]^T + bias[N]
// CTA 128x128, BK=16 words (32 fp16), 256 threads (8 warps 2x4, warp 64x32).
// (best-measured config: R14/R15)
// ---------------------------------------------------------------------------
#define GBK2 16
#define SP 20
#define GSTG (128 * SP)
#define GSTGB (GSTG * 4)
#define GNSTG 4
#define GSM_DYN (GNSTG * 2 * GSTGB)     // 81920 bytes

__global__ void __launch_bounds__(256, 2) gemm_f16_mma(
    const uint32_t* __restrict__ A, const uint32_t* __restrict__ Bt,
    const float* __restrict__ bias, void* __restrict__ Cout,
    int M, int N, int K2, int outHalf)
{
    extern __shared__ uint32_t dsm[];
    uint32_t* Asm = dsm;
    uint32_t* Bsm = dsm + GNSTG * GSTG;

    const int tid = threadIdx.x;
    const int wid = tid >> 5;
    const int lane = tid & 31;
    const int g = lane >> 2;
    const int q = lane & 3;
    const int i8 = lane & 7, mh = lane >> 3;

    const int wm = (wid >> 2) * 64;
    const int wn = (wid & 3) * 32;

    const int mtile = blockIdx.y;
    const int ntile = blockIdx.x;

    const uint32_t* Ag = A + (size_t)mtile * 128 * K2;
    const uint32_t* Bg = Bt + (size_t)ntile * 128 * K2;

    const uint32_t asA = (uint32_t)__cvta_generic_to_shared(Asm);
    const uint32_t asB = (uint32_t)__cvta_generic_to_shared(Bsm);

    uint32_t aAddr[4];
    #pragma unroll
    for (int mi = 0; mi < 4; mi++)
        aAddr[mi] = asA + ((wm + mi * 16 + i8 + (mh & 1) * 8) * SP + (mh >> 1) * 4) * 4;
    uint32_t bAddr[2];
    #pragma unroll
    for (int j = 0; j < 2; j++)
        bAddr[j] = asB + ((wn + (2 * j + (mh >> 1)) * 8 + i8) * SP + (mh & 1) * 4) * 4;

    const int lr = tid >> 2, lc = tid & 3;
    const int nchunk = K2 / GBK2;

    // prologue: stages 0,1,2
    #pragma unroll
    for (int s = 0; s < 3; s++) {
        const int k0 = s * GBK2;
        const uint32_t boff = (uint32_t)(s * GSTG) * 4;
        #pragma unroll
        for (int i = 0; i < 2; i++) {
            const int r = lr + i * 64;
            const uint32_t doff = boff + (uint32_t)(r * SP + lc * 4) * 4;
            cp_async16(asA + doff, Ag + (size_t)r * K2 + k0 + lc * 4);
            cp_async16(asB + doff, Bg + (size_t)r * K2 + k0 + lc * 4);
        }
        CP_COMMIT();
    }

    float acc[4][4][4];
    #pragma unroll
    for (int mi = 0; mi < 4; mi++)
        #pragma unroll
        for (int ni = 0; ni < 4; ni++)
            #pragma unroll
            for (int r = 0; r < 4; r++) acc[mi][ni][r] = 0.f;

    int stage = 0;
    for (int ch = 0; ch < nchunk; ch++) {
        CP_WAIT(2);
        __syncthreads();

        if (ch + 3 < nchunk) {
            const int k0 = (ch + 3) * GBK2;
            int ps = stage + 3; if (ps >= GNSTG) ps -= GNSTG;
            const uint32_t boff = (uint32_t)(ps * GSTG) * 4;
            #pragma unroll
            for (int i = 0; i < 2; i++) {
                const int r = lr + i * 64;
                const uint32_t doff = boff + (uint32_t)(r * SP + lc * 4) * 4;
                cp_async16(asA + doff, Ag + (size_t)r * K2 + k0 + lc * 4);
                cp_async16(asB + doff, Bg + (size_t)r * K2 + k0 + lc * 4);
            }
        }
        CP_COMMIT();

        const uint32_t bufoff = (uint32_t)stage * GSTGB;
        #pragma unroll
        for (int ks = 0; ks < GBK2; ks += 8) {
            const uint32_t coff = bufoff + ks * 4;
            uint32_t af[4][4], bf[4][2];
            #pragma unroll
            for (int mi = 0; mi < 4; mi++)
                ldsm_x4(af[mi], aAddr[mi] + coff);
            #pragma unroll
            for (int j = 0; j < 2; j++) {
                uint32_t t[4];
                ldsm_x4(t, bAddr[j] + coff);
                bf[2 * j][0] = t[0]; bf[2 * j][1] = t[1];
                bf[2 * j + 1][0] = t[2]; bf[2 * j + 1][1] = t[3];
            }
            #pragma unroll
            for (int mi = 0; mi < 4; mi++)
                #pragma unroll
                for (int ni = 0; ni < 4; ni++)
                    mma_f16(acc[mi][ni], af[mi][0], af[mi][1], af[mi][2], af[mi][3],
                            bf[ni][0], bf[ni][1]);
        }
        if (++stage == GNSTG) stage = 0;
    }

    const int rowbase = mtile * 128 + wm;
    const int colbase = ntile * 128 + wn;
    if (outHalf) {
        uint32_t* Ch = (uint32_t*)Cout;
        const int Nw = N >> 1;
        #pragma unroll
        for (int mi = 0; mi < 4; mi++) {
            #pragma unroll
            for (int ni = 0; ni < 4; ni++) {
                const int col = colbase + ni * 8 + 2 * q;
                const float bx = bias[col], by = bias[col + 1];
                const int r0 = rowbase + mi * 16 + g;
                const int wcol = col >> 1;
                Ch[(size_t)r0 * Nw + wcol] = pack_h2(acc[mi][ni][0] + bx, acc[mi][ni][1] + by);
                Ch[(size_t)(r0 + 8) * Nw + wcol] = pack_h2(acc[mi][ni][2] + bx, acc[mi][ni][3] + by);
            }
        }
    } else {
        float* Cf = (float*)Cout;
        #pragma unroll
        for (int mi = 0; mi < 4; mi++) {
            #pragma unroll
            for (int ni = 0; ni < 4; ni++) {
                const int col = colbase + ni * 8 + 2 * q;
                const float bx = bias[col], by = bias[col + 1];
                const int r0 = rowbase + mi * 16 + g;
                float2 v0 = make_float2(acc[mi][ni][0] + bx, acc[mi][ni][1] + by);
                float2 v1 = make_float2(acc[mi][ni][2] + bx, acc[mi][ni][3] + by);
                *(float2*)(Cf + (size_t)r0 * N + col) = v0;
                *(float2*)(Cf + (size_t)(r0 + 8) * N + col) = v1;
            }
        }
    }
}

// ---------------------------------------------------------------------------
// fp16 flash attention (64 queries/CTA, 128 threads):
// cp.async double-buffered K/V, V via ldmatrix.trans, P in registers,
// log2 softmax with f16x2 ex2, row-sums l via ones-MMA, mask fast-path.
// ---------------------------------------------------------------------------
#define FBQ 64
#define FKV 64
#define AP 36
#define ATILE (FKV * AP)
#define ATILEB (ATILE * 4)
#define ONES_H2 0x3C003C00u

__global__ void __launch_bounds__(128) flash_attn_f16(
    const uint32_t* __restrict__ kqvh, const int* __restrict__ pmask,
    uint32_t* __restrict__ yh)
{
    __shared__ uint32_t Ksh[2][ATILE];
    __shared__ uint32_t Vsh[2][ATILE];
    __shared__ uint32_t Qsh[FBQ * AP];
    __shared__ int pm_sh[2][FKV];

    const int qt = (T_ / FBQ - 1) - blockIdx.x;
    const int bh = blockIdx.y;
    const int b = bh / H_, h = bh % H_;
    const int tid = threadIdx.x;
    const int wid = tid >> 5, lane = tid & 31;
    const int g = lane >> 2, q = lane & 3;
    const int i8 = lane & 7, mh = lane >> 3;
    const int m0 = wid * 16;

    const uint32_t* baseW = kqvh + (size_t)b * T_ * KQV_W + h * 32;
    const int* pmrow = pmask + b * T_;

    const uint32_t sK = (uint32_t)__cvta_generic_to_shared(&Ksh[0][0]);
    const uint32_t sV = (uint32_t)__cvta_generic_to_shared(&Vsh[0][0]);
    const uint32_t sPM = (uint32_t)__cvta_generic_to_shared(&pm_sh[0][0]);

    uint32_t kAddr[4];
    #pragma unroll
    for (int j = 0; j < 4; j++)
        kAddr[j] = sK + (((2 * j + (mh >> 1)) * 8 + i8) * AP + (mh & 1) * 4) * 4;
    uint32_t vAddr[4];
    #pragma unroll
    for (int j = 0; j < 4; j++)
        vAddr[j] = sV + ((i8 + (mh & 1) * 8) * AP + (2 * j + (mh >> 1)) * 4) * 4;

    const int ir = tid >> 3, ic = tid & 7;

    // ---- load Q tile, scale by log2(e)/sqrt(D) ----
    const float qscale = 0.125f * 1.4426950408889634f;
    #pragma unroll
    for (int it = 0; it < 4; it++) {
        const int idx = tid + it * 128;
        const int r = idx >> 3, c4 = idx & 7;
        uint4 w = *(const uint4*)(baseW + (C_ / 2) + (size_t)(qt * FBQ + r) * KQV_W + c4 * 4);
        uint32_t* ww = &w.x;
        uint32_t out[4];
        #pragma unroll
        for (int k = 0; k < 4; k++) {
            __half2 hv = *reinterpret_cast<__half2*>(&ww[k]);
            float2 f = __half22float2(hv);
            out[k] = pack_h2(f.x * qscale, f.y * qscale);
        }
        *(uint4*)&Qsh[r * AP + c4 * 4] = *(uint4*)out;
    }

    // prologue: prefetch tile 0 into buf 0
    {
        #pragma unroll
        for (int it = 0; it < 4; it++) {
            const int r = ir + it * 16;
            const uint32_t doff = (uint32_t)(r * AP + ic * 4) * 4;
            cp_async16(sK + doff, baseW + (size_t)r * KQV_W + ic * 4);
            cp_async16(sV + doff, baseW + 2 * (C_ / 2) + (size_t)r * KQV_W + ic * 4);
        }
        if (tid < 16) cp_async16(sPM + tid * 16, pmrow + tid * 4);
        CP_COMMIT();
    }
    __syncthreads();

    // ---- Q fragments ----
    uint32_t qf[4][4];
    #pragma unroll
    for (int kk = 0; kk < 4; kk++) {
        qf[kk][0] = Qsh[(m0 + g) * AP + kk * 8 + q];
        qf[kk][1] = Qsh[(m0 + 8 + g) * AP + kk * 8 + q];
        qf[kk][2] = Qsh[(m0 + g) * AP + kk * 8 + q + 4];
        qf[kk][3] = Qsh[(m0 + 8 + g) * AP + kk * 8 + q + 4];
    }

    float o[8][4];
    #pragma unroll
    for (int ni = 0; ni < 8; ni++)
        #pragma unroll
        for (int r = 0; r < 4; r++) o[ni][r] = 0.f;

    float lacc[4] = {0.f, 0.f, 0.f, 0.f};   // row-sum accumulator via ones-MMA
    float mr0 = -INFINITY, mr1 = -INFINITY;

    const int r0g = qt * FBQ + m0 + g;
    const int r1g = r0g + 8;

    for (int kt = 0; kt <= qt; kt++) {
        const int cur = kt & 1;
        const int kbase = kt * FKV;

        if (kt < qt) {
            const int nb = kbase + FKV;
            const uint32_t boff = (uint32_t)((cur ^ 1) * ATILE) * 4;
            #pragma unroll
            for (int it = 0; it < 4; it++) {
                const int r = ir + it * 16;
                const uint32_t doff = boff + (uint32_t)(r * AP + ic * 4) * 4;
                cp_async16(sK + doff, baseW + (size_t)(nb + r) * KQV_W + ic * 4);
                cp_async16(sV + doff, baseW + 2 * (C_ / 2) + (size_t)(nb + r) * KQV_W + ic * 4);
            }
            if (tid < 16) cp_async16(sPM + (cur ^ 1) * 256 + tid * 16, pmrow + nb + tid * 4);
            CP_COMMIT();
            CP_WAIT(1);
        } else {
            CP_WAIT(0);
        }
        __syncthreads();

        const uint32_t bufoff = (uint32_t)cur * ATILEB;

        // ---- S = Q K^T ----
        float s[8][4];
        #pragma unroll
        for (int ni = 0; ni < 8; ni++)
            #pragma unroll
            for (int r = 0; r < 4; r++) s[ni][r] = 0.f;

        #pragma unroll
        for (int kk = 0; kk < 4; kk++) {
            const uint32_t coff = bufoff + kk * 32;
            #pragma unroll
            for (int j = 0; j < 4; j++) {
                uint32_t t[4];
                ldsm_x4(t, kAddr[j] + coff);
                mma_f16(s[2 * j],     qf[kk][0], qf[kk][1], qf[kk][2], qf[kk][3], t[0], t[1]);
                mma_f16(s[2 * j + 1], qf[kk][0], qf[kk][1], qf[kk][2], qf[kk][3], t[2], t[3]);
            }
        }

        // ---- mask + tile max (fast path: fully-valid, non-diagonal tile) ----
        const bool diag = (kt == qt);
        const bool allv = __all_sync(0xffffffffu,
            (pm_sh[cur][lane] != 0) & (pm_sh[cur][lane + 32] != 0));
        float mt0 = -INFINITY, mt1 = -INFINITY;
        if (!diag && allv) {
            #pragma unroll
            for (int ni = 0; ni < 8; ni++) {
                mt0 = fmaxf(mt0, fmaxf(s[ni][0], s[ni][1]));
                mt1 = fmaxf(mt1, fmaxf(s[ni][2], s[ni][3]));
            }
        } else {
            #pragma unroll
            for (int ni = 0; ni < 8; ni++) {
                const int c0 = ni * 8 + 2 * q, c1 = c0 + 1;
                const bool pm0 = pm_sh[cur][c0] != 0, pm1 = pm_sh[cur][c1] != 0;
                const int gc0 = kbase + c0, gc1 = kbase + c1;
                if (!(pm0 && (!diag || gc0 <= r0g))) s[ni][0] = -1e30f;
                if (!(pm1 && (!diag || gc1 <= r0g))) s[ni][1] = -1e30f;
                if (!(pm0 && (!diag || gc0 <= r1g))) s[ni][2] = -1e30f;
                if (!(pm1 && (!diag || gc1 <= r1g))) s[ni][3] = -1e30f;
                mt0 = fmaxf(mt0, fmaxf(s[ni][0], s[ni][1]));
                mt1 = fmaxf(mt1, fmaxf(s[ni][2], s[ni][3]));
            }
        }
        mt0 = fmaxf(mt0, __shfl_xor_sync(0xffffffffu, mt0, 1));
        mt0 = fmaxf(mt0, __shfl_xor_sync(0xffffffffu, mt0, 2));
        mt1 = fmaxf(mt1, __shfl_xor_sync(0xffffffffu, mt1, 1));
        mt1 = fmaxf(mt1, __shfl_xor_sync(0xffffffffu, mt1, 2));

        const float mn0 = fmaxf(mr0, mt0), mn1 = fmaxf(mr1, mt1);
        const float ms0 = (mn0 < -1e29f) ? 0.f : mn0;
        const float ms1 = (mn1 < -1e29f) ? 0.f : mn1;
        const float corr0 = ex2(mr0 - ms0);
        const float corr1 = ex2(mr1 - ms1);
        mr0 = mn0; mr1 = mn1;
        lacc[0] *= corr0; lacc[1] *= corr0;
        lacc[2] *= corr1; lacc[3] *= corr1;
        #pragma unroll
        for (int ni = 0; ni < 8; ni++) {
            o[ni][0] *= corr0; o[ni][1] *= corr0;
            o[ni][2] *= corr1; o[ni][3] *= corr1;
        }

        // ---- P = 2^(S-m) via packed f16x2 ex2, directly into A-frag regs ----
        uint32_t pf[8][2];
        #pragma unroll
        for (int ni = 0; ni < 8; ni++) {
            pf[ni][0] = ex2_h2(pack_h2(s[ni][0] - ms0, s[ni][1] - ms0));
            pf[ni][1] = ex2_h2(pack_h2(s[ni][2] - ms1, s[ni][3] - ms1));
        }

        // ---- l += P @ ones (row sums via MMA; every quad lane gets full sum) ----
        #pragma unroll
        for (int kk = 0; kk < 4; kk++)
            mma_f16(lacc, pf[2 * kk][0], pf[2 * kk][1],
                    pf[2 * kk + 1][0], pf[2 * kk + 1][1], ONES_H2, ONES_H2);

        // ---- O += P V  (B frags via ldmatrix.trans from natural V rows) ----
        #pragma unroll
        for (int kk = 0; kk < 4; kk++) {
            const uint32_t coff = bufoff + (uint32_t)(kk * 16 * AP) * 4;
            const uint32_t a0 = pf[2 * kk][0], a1 = pf[2 * kk][1];
            const uint32_t a2 = pf[2 * kk + 1][0], a3 = pf[2 * kk + 1][1];
            #pragma unroll
            for (int j = 0; j < 4; j++) {
                uint32_t t[4];
                ldsm_x4_trans(t, vAddr[j] + coff);
                mma_f16(o[2 * j],     a0, a1, a2, a3, t[0], t[1]);
                mma_f16(o[2 * j + 1], a0, a1, a2, a3, t[2], t[3]);
            }
        }
        __syncthreads();
    }

    // ---- finalize (lacc[0]/lacc[2] hold full row sums; no shuffles) ----
    const float inv0 = 1.f / lacc[0], inv1 = 1.f / lacc[2];

    #pragma unroll
    for (int ni = 0; ni < 8; ni++) {
        const int wcol = h * 32 + ni * 4 + q;
        yh[(size_t)(b * T_ + r0g) * YW + wcol] = pack_h2(o[ni][0] * inv0, o[ni][1] * inv0);
        yh[(size_t)(b * T_ + r1g) * YW + wcol] = pack_h2(o[ni][2] * inv1, o[ni][3] * inv1);
    }
}

// ---------------------------------------------------------------------------
extern "C" void kernel_launch(void* const* d_in, const int* in_sizes, int n_in,
                              void* d_out, int out_size)
{
    const float* x      = (const float*)d_in[0];
    const float* W_kqv  = (const float*)d_in[1];
    const float* b_kqv  = (const float*)d_in[2];
    const float* W_proj = (const float*)d_in[3];
    const float* b_proj = (const float*)d_in[4];
    const int*   pmask  = (const int*)d_in[5];
    float* out = (float*)d_out;

    uint32_t *xh, *wkqvTh, *wprojTh, *kqvh, *yh;
    cudaGetSymbolAddress((void**)&xh, g_xh);
    cudaGetSymbolAddress((void**)&wkqvTh, g_wkqvTh);
    cudaGetSymbolAddress((void**)&wprojTh, g_wprojTh);
    cudaGetSymbolAddress((void**)&kqvh, g_kqvh);
    cudaGetSymbolAddress((void**)&yh, g_yh);

    cudaFuncSetAttribute(gemm_f16_mma,
                         cudaFuncAttributeMaxDynamicSharedMemorySize, GSM_DYN);

    // 0) convert x and weights to fp16
    {
        int nw = M_ * C_ / 2;
        cvt_f32_to_h2<<<(nw + 255) / 256, 256>>>(x, xh, nw);
        dim3 g1(C3_ / 32, C_ / 32);
        transpose_h<<<g1, dim3(32, 8)>>>(W_kqv, (__half*)wkqvTh, C_, C3_);
        dim3 g2(C_ / 32, C_ / 32);
        transpose_h<<<g2, dim3(32, 8)>>>(W_proj, (__half*)wprojTh, C_, C_);
    }
    // 1) kqv = x @ W_kqv + b_kqv
    {
        dim3 grid(C3_ / 128, M_ / 128);
        gemm_f16_mma<<<grid, 256, GSM_DYN>>>(xh, wkqvTh, b_kqv, kqvh, M_, C3_, K2_, 1);
    }
    // 2) flash attention (64 queries/CTA, 128 threads)
    {
        dim3 grid(T_ / FBQ, B_ * H_);
        flash_attn_f16<<<grid, 128>>>(kqvh, pmask, yh);
    }
    // 3) out = y @ W_proj + b_proj
    {
        dim3 grid(C_ / 128, M_ / 128);
        gemm_f16_mma<<<grid, 256, GSM_DYN>>>(yh, wprojTh, b_proj, out, M_, C_, K2_, 0);
    }
}